// round 1
// baseline (speedup 1.0000x reference)
#include <cuda_runtime.h>
#include <cuda_bf16.h>
#include <math.h>

#define B_  4
#define T_  2048
#define C_  768
#define NH_ 12
#define HD_ 64
#define RD_ 16
#define M_  (B_ * T_)          // 8192
#define NQKV (3 * C_)          // 2304

// ---------------- scratch (device globals; no allocation allowed) ------------
__device__ float g_qkv[M_ * NQKV];               // [B*T, 2304]
__device__ float g_q[B_ * NH_ * T_ * HD_];       // [BH, T, 64]
__device__ float g_k[B_ * NH_ * T_ * HD_];
__device__ float g_v[B_ * NH_ * T_ * HD_];
__device__ float g_o[M_ * C_];                   // [B*T, 768] attention output

// ---------------- GEMM: C[m,n] = sum_k A[m,k] * B[n,k] -----------------------
// A: [M,K] row-major, B: [N,K] row-major (i.e. C = A @ B^T)
// BM=BN=64, BK=32, 256 threads, 4x4 per-thread tile.
#define GBM 64
#define GBN 64
#define GBK 32
#define GPAD 68   // row stride (floats), 16B-aligned, conflict-friendly

__global__ __launch_bounds__(256) void gemm_tn_kernel(
    const float* __restrict__ A, const float* __restrict__ Bm,
    float* __restrict__ C, int M, int N, int K)
{
    __shared__ float As[GBK * GPAD];  // As[k][m]
    __shared__ float Bs[GBK * GPAD];  // Bs[k][n]

    const int tid = threadIdx.x;
    const int tx = tid & 15;          // col group
    const int ty = tid >> 4;          // row group
    const int m0 = blockIdx.y * GBM;
    const int n0 = blockIdx.x * GBN;

    float acc[4][4];
#pragma unroll
    for (int i = 0; i < 4; i++)
#pragma unroll
        for (int j = 0; j < 4; j++) acc[i][j] = 0.f;

    for (int k0 = 0; k0 < K; k0 += GBK) {
        // load A tile 64x32 and B tile 64x32, store transposed
#pragma unroll
        for (int l = 0; l < 8; l++) {
            int idx = l * 256 + tid;
            int mm = idx >> 5;        // 0..63
            int kk = idx & 31;        // 0..31
            As[kk * GPAD + mm] = A[(size_t)(m0 + mm) * K + k0 + kk];
            Bs[kk * GPAD + mm] = Bm[(size_t)(n0 + mm) * K + k0 + kk];
        }
        __syncthreads();

#pragma unroll
        for (int kk = 0; kk < GBK; kk++) {
            float4 a = *(const float4*)&As[kk * GPAD + ty * 4];
            float4 b = *(const float4*)&Bs[kk * GPAD + tx * 4];
            float av[4] = {a.x, a.y, a.z, a.w};
            float bv[4] = {b.x, b.y, b.z, b.w};
#pragma unroll
            for (int i = 0; i < 4; i++)
#pragma unroll
                for (int j = 0; j < 4; j++) acc[i][j] += av[i] * bv[j];
        }
        __syncthreads();
    }

#pragma unroll
    for (int i = 0; i < 4; i++) {
        float4 o = make_float4(acc[i][0], acc[i][1], acc[i][2], acc[i][3]);
        *(float4*)&C[(size_t)(m0 + ty * 4 + i) * N + n0 + tx * 4] = o;
    }
}

// ---------------- RoPE + rearrange: qkv[B*T,2304] -> q/k/v [BH,T,64] ---------
__global__ __launch_bounds__(256) void rope_rearrange_kernel()
{
    const long long total = 3LL * B_ * NH_ * T_ * HD_;
    long long idx = (long long)blockIdx.x * blockDim.x + threadIdx.x;
    if (idx >= total) return;

    int d = (int)(idx & 63);
    long long r = idx >> 6;
    int t = (int)(r % T_); r /= T_;
    int h = (int)(r % NH_); r /= NH_;
    int b = (int)(r % B_);
    int sel = (int)(r / B_);

    const size_t srow = ((size_t)(b * T_ + t)) * NQKV + sel * C_ + h * HD_;
    float val = g_qkv[srow + d];

    if (sel < 2 && d < RD_) {
        int j = (d < 8) ? d : d - 8;
        float freq = __powf(10000.0f, -(float)j / 8.0f);
        float ang = (float)t * freq;
        float c = cosf(ang), s = sinf(ang);
        if (d < 8) {
            float r2 = g_qkv[srow + d + 8];
            val = val * c - r2 * s;
        } else {
            float r1 = g_qkv[srow + d - 8];
            val = val * c + r1 * s;
        }
    }

    float* dst = (sel == 0) ? g_q : (sel == 1) ? g_k : g_v;
    dst[(((size_t)(b * NH_ + h)) * T_ + t) * HD_ + d] = val;
}

// ---------------- Flash attention (fp32, causal) -----------------------------
// grid: (T/64 q-tiles, B*NH), 256 threads, BLOCK_Q = BLOCK_K = 64.
#define FQ 64
#define FK 64
#define FPAD 68
#define SPAD 65

__global__ __launch_bounds__(256) void flash_kernel()
{
    extern __shared__ float sm[];
    float* QsT = sm;                      // [64][68]  (d-major: QsT[d][r])
    float* KsT = QsT + 64 * FPAD;         // [64][68]  (KsT[d][c])
    float* Vs  = KsT + 64 * FPAD;         // [64][68]  (Vs[k][d])
    float* Ss  = Vs  + 64 * FPAD;         // [64][65]
    float* m_s = Ss + 64 * SPAD;
    float* l_s = m_s + 64;
    float* al_s = l_s + 64;

    const int tid = threadIdx.x;
    const int tx = tid & 15, ty = tid >> 4;
    const int qt = blockIdx.x;
    const int bh = blockIdx.y;
    const int q0 = qt * FQ;
    const int b = bh / NH_, h = bh % NH_;
    const float scale = 0.125f;  // 1/sqrt(64)

    const float* Q = g_q + (size_t)bh * T_ * HD_;
    const float* K = g_k + (size_t)bh * T_ * HD_;
    const float* V = g_v + (size_t)bh * T_ * HD_;

    // load Q tile transposed: QsT[d][r]
#pragma unroll
    for (int l = 0; l < 16; l++) {
        int idx = l * 256 + tid;
        int rr = idx >> 6, dd = idx & 63;
        QsT[dd * FPAD + rr] = Q[(size_t)(q0 + rr) * HD_ + dd];
    }
    if (tid < 64) { m_s[tid] = -1e30f; l_s[tid] = 0.f; }

    float acc[4][4];
#pragma unroll
    for (int i = 0; i < 4; i++)
#pragma unroll
        for (int j = 0; j < 4; j++) acc[i][j] = 0.f;

    const int ktiles = qt + 1;
    for (int kt = 0; kt < ktiles; kt++) {
        const int k0 = kt * FK;
        __syncthreads();
        // load K transposed, V natural
#pragma unroll
        for (int l = 0; l < 16; l++) {
            int idx = l * 256 + tid;
            int cc = idx >> 6, dd = idx & 63;
            KsT[dd * FPAD + cc] = K[(size_t)(k0 + cc) * HD_ + dd];
            Vs[cc * FPAD + dd]  = V[(size_t)(k0 + cc) * HD_ + dd];
        }
        __syncthreads();

        // S = Q K^T
        float sacc[4][4];
#pragma unroll
        for (int i = 0; i < 4; i++)
#pragma unroll
            for (int j = 0; j < 4; j++) sacc[i][j] = 0.f;
#pragma unroll
        for (int dd = 0; dd < 64; dd++) {
            float4 a = *(const float4*)&QsT[dd * FPAD + ty * 4];
            float4 bb = *(const float4*)&KsT[dd * FPAD + tx * 4];
            float av[4] = {a.x, a.y, a.z, a.w};
            float bv[4] = {bb.x, bb.y, bb.z, bb.w};
#pragma unroll
            for (int i = 0; i < 4; i++)
#pragma unroll
                for (int j = 0; j < 4; j++) sacc[i][j] += av[i] * bv[j];
        }
        // scale + causal mask + store to Ss
        const bool diag = (kt == qt);
#pragma unroll
        for (int i = 0; i < 4; i++) {
            int gq = q0 + ty * 4 + i;
#pragma unroll
            for (int j = 0; j < 4; j++) {
                int gk = k0 + tx * 4 + j;
                float s = sacc[i][j] * scale;
                if (diag && gk > gq) s = -1e30f;
                Ss[(ty * 4 + i) * SPAD + tx * 4 + j] = s;
            }
        }
        __syncthreads();

        // online softmax (one thread per row)
        if (tid < 64) {
            int row = tid;
            float mold = m_s[row];
            float mmax = mold;
#pragma unroll 8
            for (int j = 0; j < 64; j++) mmax = fmaxf(mmax, Ss[row * SPAD + j]);
            float alpha = __expf(mold - mmax);
            float sum = 0.f;
#pragma unroll 8
            for (int j = 0; j < 64; j++) {
                float p = __expf(Ss[row * SPAD + j] - mmax);
                Ss[row * SPAD + j] = p;
                sum += p;
            }
            l_s[row] = l_s[row] * alpha + sum;
            m_s[row] = mmax;
            al_s[row] = alpha;
        }
        __syncthreads();

        // O = O*alpha + P V
        float alr[4];
#pragma unroll
        for (int i = 0; i < 4; i++) alr[i] = al_s[ty * 4 + i];
#pragma unroll
        for (int i = 0; i < 4; i++)
#pragma unroll
            for (int j = 0; j < 4; j++) acc[i][j] *= alr[i];

#pragma unroll
        for (int kk = 0; kk < 64; kk++) {
            float4 bv4 = *(const float4*)&Vs[kk * FPAD + tx * 4];
            float bv[4] = {bv4.x, bv4.y, bv4.z, bv4.w};
#pragma unroll
            for (int i = 0; i < 4; i++) {
                float a = Ss[(ty * 4 + i) * SPAD + kk];
#pragma unroll
                for (int j = 0; j < 4; j++) acc[i][j] += a * bv[j];
            }
        }
    }
    __syncthreads();

    // write O into [B*T, 768] layout (normalize by l)
#pragma unroll
    for (int i = 0; i < 4; i++) {
        float inv_l = 1.0f / l_s[ty * 4 + i];
        int t = q0 + ty * 4 + i;
        float4 o = make_float4(acc[i][0] * inv_l, acc[i][1] * inv_l,
                               acc[i][2] * inv_l, acc[i][3] * inv_l);
        *(float4*)&g_o[((size_t)(b * T_ + t)) * C_ + h * HD_ + tx * 4] = o;
    }
}

// ---------------- launch ------------------------------------------------------
extern "C" void kernel_launch(void* const* d_in, const int* in_sizes, int n_in,
                              void* d_out, int out_size)
{
    const float* x     = (const float*)d_in[0];   // [4,2048,768]
    const float* w_qkv = (const float*)d_in[1];   // [2304,768]
    const float* w_out = (const float*)d_in[2];   // [768,768]
    float* out = (float*)d_out;                   // [4,2048,768]

    float *qkv_p, *o_p;
    cudaGetSymbolAddress((void**)&qkv_p, g_qkv);
    cudaGetSymbolAddress((void**)&o_p, g_o);

    // 1) QKV GEMM: [8192,768] @ [2304,768]^T -> [8192,2304]
    {
        dim3 grid(NQKV / GBN, M_ / GBM);
        gemm_tn_kernel<<<grid, 256>>>(x, w_qkv, qkv_p, M_, NQKV, C_);
    }

    // 2) RoPE + rearrange
    {
        long long total = 3LL * B_ * NH_ * T_ * HD_;
        int blocks = (int)((total + 255) / 256);
        rope_rearrange_kernel<<<blocks, 256>>>();
    }

    // 3) flash attention
    {
        const int smem = (3 * 64 * FPAD + 64 * SPAD + 3 * 64) * sizeof(float);
        cudaFuncSetAttribute(flash_kernel, cudaFuncAttributeMaxDynamicSharedMemorySize, smem);
        dim3 grid(T_ / FQ, B_ * NH_);
        flash_kernel<<<grid, 256, smem>>>();
    }

    // 4) out projection: [8192,768] @ [768,768]^T -> [8192,768]
    {
        dim3 grid(C_ / GBN, M_ / GBM);
        gemm_tn_kernel<<<grid, 256>>>(o_p, w_out, out, M_, C_, C_);
    }
}